// round 16
// baseline (speedup 1.0000x reference)
#include <cuda_runtime.h>
#include <cuda_bf16.h>
#include <cstdint>

#define BB   8
#define SS   1024
#define DD   768
#define HH   8
#define DKK  96
#define FFD  1024
#define NR   (BB * SS)        // 8192 rows
#define NBH  (BB * HH)        // 64 (b,h) pairs

// ---------------- scratch (static device globals; no allocation) ----------------
__device__ float g_kv[NR * DD];
__device__ float g_w [(size_t)NBH * SS * SS];   // score matrix (fp32); masked tiles/rows unwritten
__device__ float g_cm [NBH * SS];
__device__ float g_ics[NBH * SS];
__device__ float g_pm [NBH * 8 * SS];
__device__ float g_ps [NBH * 8 * SS];
__device__ float g_o [NR * DD];
__device__ float g_x1[NR * DD];
__device__ float g_x2[NR * DD];
__device__ unsigned char g_mask[NR];
__device__ int g_flags[2];
__device__ __nv_bfloat16 g_a2 [(size_t)NR * 2304];        // split A (K=768 layout)
__device__ __nv_bfloat16 g_a2h[(size_t)NR * 3072];        // split h (K=1024 layout)
__device__ __nv_bfloat16 g_b2t[(size_t)1024 * 3 * 1024];  // split W^T
__device__ __nv_bfloat16 g_qs [(size_t)NBH * SS * 384];   // q  split [hi|hi|lo], DK pad 128 (pad stays 0)
__device__ __nv_bfloat16 g_ks [(size_t)NBH * SS * 384];   // kv split [hi|lo|hi]
__device__ __nv_bfloat16 g_vt [(size_t)BB * DD * 2048];   // V^T split [hi|lo] per batch

#define SWZ128(o) ((o) ^ (((o) >> 3) & 0x70))

__device__ __forceinline__ uint32_t smem_u32(const void* p) {
    uint32_t a;
    asm("{ .reg .u64 t; cvta.to.shared.u64 t, %1; cvt.u32.u64 %0, t; }" : "=r"(a) : "l"(p));
    return a;
}

__device__ __forceinline__ void split2(float x, float y, uint32_t& hi, uint32_t& lo)
{
    __nv_bfloat16 hx = __float2bfloat16(x);
    __nv_bfloat16 hy = __float2bfloat16(y);
    __nv_bfloat16 lx = __float2bfloat16(x - __bfloat162float(hx));
    __nv_bfloat16 ly = __float2bfloat16(y - __bfloat162float(hy));
    hi = (uint32_t)*(uint16_t*)&hx | ((uint32_t)*(uint16_t*)&hy << 16);
    lo = (uint32_t)*(uint16_t*)&lx | ((uint32_t)*(uint16_t*)&ly << 16);
}

// ================= bf16 split conversions =======================================
__global__ void split_a_kernel(const float* __restrict__ X,
                               __nv_bfloat16* __restrict__ A2, int K)
{
    int idx = blockIdx.x * 256 + threadIdx.x;
    int r = idx / K, k = idx - r * K;
    float v = X[idx];
    __nv_bfloat16 h = __float2bfloat16(v);
    __nv_bfloat16 l = __float2bfloat16(v - __bfloat162float(h));
    __nv_bfloat16* row = A2 + (size_t)r * 3 * K;
    row[k] = h; row[K + k] = h; row[2 * K + k] = l;
}

__global__ void split_wt_kernel(const float* __restrict__ W,
                                __nv_bfloat16* __restrict__ Bt, int K, int N)
{
    __shared__ float t[32][33];
    int nb = blockIdx.x * 32, kb = blockIdx.y * 32;
    int x = threadIdx.x, y = threadIdx.y;          // 32 x 8
#pragma unroll
    for (int yy = 0; yy < 32; yy += 8)
        t[y + yy][x] = W[(size_t)(kb + y + yy) * N + nb + x];
    __syncthreads();
    const size_t K3 = 3 * (size_t)K;
#pragma unroll
    for (int yy = 0; yy < 32; yy += 8) {
        int n = nb + y + yy;
        int k = kb + x;
        float v = t[x][y + yy];
        __nv_bfloat16 h = __float2bfloat16(v);
        __nv_bfloat16 l = __float2bfloat16(v - __bfloat162float(h));
        Bt[(size_t)n * K3 + k] = h;
        Bt[(size_t)n * K3 + K + k] = l;
        Bt[(size_t)n * K3 + 2 * K + k] = h;
    }
}

// kv per batch [1024 k, 768 n] -> vt[b][n][2048] planes [hi|lo]
__global__ void split_vt_kernel(const float* __restrict__ kv,
                                __nv_bfloat16* __restrict__ vt)
{
    __shared__ float t[32][33];
    int b = blockIdx.z;
    const float* W = kv + (size_t)b * SS * DD;
    __nv_bfloat16* Bt = vt + (size_t)b * DD * 2048;
    int nb = blockIdx.x * 32, kb = blockIdx.y * 32;
    int x = threadIdx.x, y = threadIdx.y;
#pragma unroll
    for (int yy = 0; yy < 32; yy += 8)
        t[y + yy][x] = W[(size_t)(kb + y + yy) * DD + nb + x];
    __syncthreads();
#pragma unroll
    for (int yy = 0; yy < 32; yy += 8) {
        int n = nb + y + yy;
        int k = kb + x;
        float v = t[x][y + yy];
        __nv_bfloat16 h = __float2bfloat16(v);
        __nv_bfloat16 l = __float2bfloat16(v - __bfloat162float(h));
        Bt[(size_t)n * 2048 + k] = h;
        Bt[(size_t)n * 2048 + 1024 + k] = l;
    }
}

// ================= HMMA dense GEMM with fused-output modes ======================
// MODE 0: C = A@B + bias (fp32)
// MODE 2: qs-split output only (PAIR0 [hi|hi|lo], per-head 128-pad layout)
// MODE 3: fp32 C AND ks-split (PAIR1 [hi|lo|hi])
// MODE 4: relu, h-split output only (K=1024 row layout [hi|hi|lo])
#define GEMM_SMEM_BYTES 65536

template <int MODE>
__global__ __launch_bounds__(256)
void mma_gemm(const __nv_bfloat16* __restrict__ A2, const __nv_bfloat16* __restrict__ Bt,
              const float* __restrict__ bias, float* __restrict__ C,
              __nv_bfloat16* __restrict__ sp, int N, int Kp)
{
    extern __shared__ char smem[];
    const uint32_t sb = smem_u32(smem);
    const int tid = threadIdx.x, wid = tid >> 5, lid = tid & 31;
    const int row0 = blockIdx.y << 7, col0 = blockIdx.x << 7;
    const int wr = (wid & 1) << 6;
    const int wc = (wid >> 1) << 5;

    const int gr = tid >> 3;
    const int gc = tid & 7;

    const int a_row = (lid & 7) + ((lid >> 3) & 1) * 8;
    const int a_kb  = (lid >> 4) * 8;
    const int b_row = (lid & 7);
    const int b_kb  = ((lid >> 3) & 1) * 8;

    float acc[4][4][4];
#pragma unroll
    for (int mi = 0; mi < 4; mi++)
#pragma unroll
        for (int ni = 0; ni < 4; ni++)
#pragma unroll
            for (int r = 0; r < 4; r++) acc[mi][ni][r] = 0.f;

    const int niter = Kp >> 6;

    {
        const __nv_bfloat16* Ag = A2 + (size_t)row0 * Kp;
        const __nv_bfloat16* Bg = Bt + (size_t)col0 * Kp;
#pragma unroll
        for (int t = 0; t < 4; t++) {
            int r = gr + (t << 5);
            uint32_t off = (uint32_t)((r << 7) + (gc << 4));
            *(uint4*)(smem + SWZ128(off)) =
                *(const uint4*)(Ag + (size_t)r * Kp + (gc << 3));
            *(uint4*)(smem + 16384 + SWZ128(off)) =
                *(const uint4*)(Bg + (size_t)r * Kp + (gc << 3));
        }
    }
    __syncthreads();

    for (int i = 0; i < niter; i++) {
        uint4 ra[4], rb[4];
        if (i + 1 < niter) {
            const __nv_bfloat16* Ag = A2 + (size_t)row0 * Kp + ((i + 1) << 6);
            const __nv_bfloat16* Bg = Bt + (size_t)col0 * Kp + ((i + 1) << 6);
#pragma unroll
            for (int t = 0; t < 4; t++) {
                int r = gr + (t << 5);
                ra[t] = *(const uint4*)(Ag + (size_t)r * Kp + (gc << 3));
                rb[t] = *(const uint4*)(Bg + (size_t)r * Kp + (gc << 3));
            }
        }

        const uint32_t sA = sb + (uint32_t)((i & 1) * 32768);
        const uint32_t sB = sA + 16384;
#pragma unroll
        for (int kk = 0; kk < 4; kk++) {
            uint32_t af[4][4], bf[4][2];
#pragma unroll
            for (int mi = 0; mi < 4; mi++) {
                uint32_t off = (uint32_t)(((wr + mi * 16 + a_row) << 7) +
                                          ((kk * 16 + a_kb) << 1));
                asm volatile("ldmatrix.sync.aligned.m8n8.x4.shared.b16 {%0,%1,%2,%3}, [%4];"
                             : "=r"(af[mi][0]), "=r"(af[mi][1]), "=r"(af[mi][2]), "=r"(af[mi][3])
                             : "r"(sA + SWZ128(off)));
            }
#pragma unroll
            for (int ni = 0; ni < 4; ni++) {
                uint32_t off = (uint32_t)(((wc + ni * 8 + b_row) << 7) +
                                          ((kk * 16 + b_kb) << 1));
                asm volatile("ldmatrix.sync.aligned.m8n8.x2.shared.b16 {%0,%1}, [%2];"
                             : "=r"(bf[ni][0]), "=r"(bf[ni][1])
                             : "r"(sB + SWZ128(off)));
            }
#pragma unroll
            for (int mi = 0; mi < 4; mi++)
#pragma unroll
                for (int ni = 0; ni < 4; ni++) {
                    asm volatile(
                        "mma.sync.aligned.m16n8k16.row.col.f32.bf16.bf16.f32 "
                        "{%0,%1,%2,%3}, {%4,%5,%6,%7}, {%8,%9}, {%0,%1,%2,%3};"
                        : "+f"(acc[mi][ni][0]), "+f"(acc[mi][ni][1]),
                          "+f"(acc[mi][ni][2]), "+f"(acc[mi][ni][3])
                        : "r"(af[mi][0]), "r"(af[mi][1]), "r"(af[mi][2]), "r"(af[mi][3]),
                          "r"(bf[ni][0]), "r"(bf[ni][1]));
                }
        }

        if (i + 1 < niter) {
            char* dst = smem + ((i + 1) & 1) * 32768;
#pragma unroll
            for (int t = 0; t < 4; t++) {
                int r = gr + (t << 5);
                uint32_t off = (uint32_t)((r << 7) + (gc << 4));
                *(uint4*)(dst + SWZ128(off)) = ra[t];
                *(uint4*)(dst + 16384 + SWZ128(off)) = rb[t];
            }
        }
        __syncthreads();
    }

    const int l4 = lid >> 2, l2 = (lid & 3) << 1;
#pragma unroll
    for (int mi = 0; mi < 4; mi++) {
#pragma unroll
        for (int ni = 0; ni < 4; ni++) {
            int rg = row0 + wr + mi * 16 + l4;
            int cg = col0 + wc + ni * 8 + l2;
            float b0 = bias[cg], b1 = bias[cg + 1];
            float v00 = acc[mi][ni][0] + b0, v01 = acc[mi][ni][1] + b1;
            float v10 = acc[mi][ni][2] + b0, v11 = acc[mi][ni][3] + b1;
            if (MODE == 4) {
                v00 = fmaxf(v00, 0.f); v01 = fmaxf(v01, 0.f);
                v10 = fmaxf(v10, 0.f); v11 = fmaxf(v11, 0.f);
            }
            if (MODE == 0 || MODE == 3) {
                *(float2*)(C + (size_t)rg * N + cg) = make_float2(v00, v01);
                *(float2*)(C + (size_t)(rg + 8) * N + cg) = make_float2(v10, v11);
            }
            if (MODE == 2 || MODE == 3) {
                // per-head 128-padded split layout (pad region stays zero-init)
                int h = cg / 96, dd = cg - h * 96;
#pragma unroll
                for (int rr = 0; rr < 2; rr++) {
                    int row = rg + rr * 8;
                    int bq = row >> 10, s = row & 1023;
                    __nv_bfloat16* op = sp + ((size_t)((bq << 3) + h) * SS + s) * 384 + dd;
                    uint32_t hi, lo;
                    if (rr == 0) split2(v00, v01, hi, lo);
                    else         split2(v10, v11, hi, lo);
                    if (MODE == 2) {         // PAIR0 [hi|hi|lo]
                        *(uint32_t*)(op) = hi; *(uint32_t*)(op + 128) = hi; *(uint32_t*)(op + 256) = lo;
                    } else {                 // PAIR1 [hi|lo|hi]
                        *(uint32_t*)(op) = hi; *(uint32_t*)(op + 128) = lo; *(uint32_t*)(op + 256) = hi;
                    }
                }
            }
            if (MODE == 4) {                 // h-split rows of 3072 [hi|hi|lo]
#pragma unroll
                for (int rr = 0; rr < 2; rr++) {
                    int row = rg + rr * 8;
                    __nv_bfloat16* op = sp + (size_t)row * 3072 + cg;
                    uint32_t hi, lo;
                    if (rr == 0) split2(v00, v01, hi, lo);
                    else         split2(v10, v11, hi, lo);
                    *(uint32_t*)(op) = hi; *(uint32_t*)(op + 1024) = hi; *(uint32_t*)(op + 2048) = lo;
                }
            }
        }
    }
}

// ================= HMMA scores + in-epilogue column stats =======================
__global__ __launch_bounds__(256)
void scores_mma(const __nv_bfloat16* __restrict__ qs,
                const __nv_bfloat16* __restrict__ ks, float* __restrict__ w,
                float* __restrict__ pm, float* __restrict__ ps)
{
    extern __shared__ char smem[];
    const uint32_t sb = smem_u32(smem);
    const int bh = blockIdx.z, b = bh >> 3;
    const int k0 = blockIdx.x << 7, q0 = blockIdx.y << 7;
    const int qt = q0 >> 7;
    const int tid = threadIdx.x, wid = tid >> 5, lid = tid & 31;

    if (k0 > q0 + 127) {    // fully causally masked tile: analytic partial only
        if (tid < 128) {
            size_t off = (((size_t)bh * 8 + qt) << 10) + k0 + tid;
            pm[off] = -1e9f;
            ps[off] = 128.f;
        }
        return;
    }

    float* wrow = w + (size_t)bh * SS * SS;
    const int wr = (wid & 1) << 6;
    const int wc = (wid >> 1) << 5;
    const int gr = tid >> 3, gc = tid & 7;
    const int a_row = (lid & 7) + ((lid >> 3) & 1) * 8;
    const int a_kb  = (lid >> 4) * 8;
    const int b_row = (lid & 7);
    const int b_kb  = ((lid >> 3) & 1) * 8;

    float acc[4][4][4];
#pragma unroll
    for (int mi = 0; mi < 4; mi++)
#pragma unroll
        for (int ni = 0; ni < 4; ni++)
#pragma unroll
            for (int r = 0; r < 4; r++) acc[mi][ni][r] = 0.f;

    const int Kp = 384, niter = 6;
    const __nv_bfloat16* Abase = qs + ((size_t)bh * SS + q0) * Kp;
    const __nv_bfloat16* Bbase = ks + ((size_t)bh * SS + k0) * Kp;

    {
#pragma unroll
        for (int t = 0; t < 4; t++) {
            int r = gr + (t << 5);
            uint32_t off = (uint32_t)((r << 7) + (gc << 4));
            *(uint4*)(smem + SWZ128(off)) =
                *(const uint4*)(Abase + (size_t)r * Kp + (gc << 3));
            *(uint4*)(smem + 16384 + SWZ128(off)) =
                *(const uint4*)(Bbase + (size_t)r * Kp + (gc << 3));
        }
    }
    __syncthreads();

    for (int i = 0; i < niter; i++) {
        uint4 ra[4], rb[4];
        if (i + 1 < niter) {
            const __nv_bfloat16* Ag = Abase + ((i + 1) << 6);
            const __nv_bfloat16* Bg = Bbase + ((i + 1) << 6);
#pragma unroll
            for (int t = 0; t < 4; t++) {
                int r = gr + (t << 5);
                ra[t] = *(const uint4*)(Ag + (size_t)r * Kp + (gc << 3));
                rb[t] = *(const uint4*)(Bg + (size_t)r * Kp + (gc << 3));
            }
        }
        const uint32_t sA = sb + (uint32_t)((i & 1) * 32768);
        const uint32_t sB = sA + 16384;
#pragma unroll
        for (int kk = 0; kk < 4; kk++) {
            uint32_t af[4][4], bf[4][2];
#pragma unroll
            for (int mi = 0; mi < 4; mi++) {
                uint32_t off = (uint32_t)(((wr + mi * 16 + a_row) << 7) +
                                          ((kk * 16 + a_kb) << 1));
                asm volatile("ldmatrix.sync.aligned.m8n8.x4.shared.b16 {%0,%1,%2,%3}, [%4];"
                             : "=r"(af[mi][0]), "=r"(af[mi][1]), "=r"(af[mi][2]), "=r"(af[mi][3])
                             : "r"(sA + SWZ128(off)));
            }
#pragma unroll
            for (int ni = 0; ni < 4; ni++) {
                uint32_t off = (uint32_t)(((wc + ni * 8 + b_row) << 7) +
                                          ((kk * 16 + b_kb) << 1));
                asm volatile("ldmatrix.sync.aligned.m8n8.x2.shared.b16 {%0,%1}, [%2];"
                             : "=r"(bf[ni][0]), "=r"(bf[ni][1])
                             : "r"(sB + SWZ128(off)));
            }
#pragma unroll
            for (int mi = 0; mi < 4; mi++)
#pragma unroll
                for (int ni = 0; ni < 4; ni++) {
                    asm volatile(
                        "mma.sync.aligned.m16n8k16.row.col.f32.bf16.bf16.f32 "
                        "{%0,%1,%2,%3}, {%4,%5,%6,%7}, {%8,%9}, {%0,%1,%2,%3};"
                        : "+f"(acc[mi][ni][0]), "+f"(acc[mi][ni][1]),
                          "+f"(acc[mi][ni][2]), "+f"(acc[mi][ni][3])
                        : "r"(af[mi][0]), "r"(af[mi][1]), "r"(af[mi][2]), "r"(af[mi][3]),
                          "r"(bf[ni][0]), "r"(bf[ni][1]));
                }
        }
        if (i + 1 < niter) {
            char* dst = smem + ((i + 1) & 1) * 32768;
#pragma unroll
            for (int t = 0; t < 4; t++) {
                int r = gr + (t << 5);
                uint32_t off = (uint32_t)((r << 7) + (gc << 4));
                *(uint4*)(dst + SWZ128(off)) = ra[t];
                *(uint4*)(dst + 16384 + SWZ128(off)) = rb[t];
            }
        }
        __syncthreads();
    }

    // ---- epilogue: mask + scale; store ONLY non-padded rows; keep acc for stats
    const float scale = 0.10206207261596577f;  // 1/sqrt(96)
    const int l4 = lid >> 2, l2 = (lid & 3) << 1;
#pragma unroll
    for (int mi = 0; mi < 4; mi++) {
        int q1 = q0 + wr + mi * 16 + l4;
        int q2 = q1 + 8;
        bool pm1 = (g_mask[b * SS + q1] != 0);
        bool pm2 = (g_mask[b * SS + q2] != 0);
#pragma unroll
        for (int ni = 0; ni < 4; ni++) {
            int cg = k0 + wc + ni * 8 + l2;
            float v00 = (pm1 || cg     > q1) ? -1e9f : acc[mi][ni][0] * scale;
            float v01 = (pm1 || cg + 1 > q1) ? -1e9f : acc[mi][ni][1] * scale;
            float v10 = (pm2 || cg     > q2) ? -1e9f : acc[mi][ni][2] * scale;
            float v11 = (pm2 || cg + 1 > q2) ? -1e9f : acc[mi][ni][3] * scale;
            if (!pm1) *(float2*)(wrow + (size_t)q1 * SS + cg) = make_float2(v00, v01);
            if (!pm2) *(float2*)(wrow + (size_t)q2 * SS + cg) = make_float2(v10, v11);
            acc[mi][ni][0] = v00; acc[mi][ni][1] = v01;
            acc[mi][ni][2] = v10; acc[mi][ni][3] = v11;
        }
    }

    // ---- column stats
    float* msm = (float*)smem;          // [2][128]
    float* ssm = msm + 256;
    float mcol[4][2], scol[4][2];
#pragma unroll
    for (int ni = 0; ni < 4; ni++) {
#pragma unroll
        for (int par = 0; par < 2; par++) {
            float m = acc[0][ni][par];
#pragma unroll
            for (int mi = 1; mi < 4; mi++) m = fmaxf(m, acc[mi][ni][par]);
#pragma unroll
            for (int mi = 0; mi < 4; mi++) m = fmaxf(m, acc[mi][ni][2 + par]);
            m = fmaxf(m, __shfl_xor_sync(0xffffffffu, m, 4));
            m = fmaxf(m, __shfl_xor_sync(0xffffffffu, m, 8));
            m = fmaxf(m, __shfl_xor_sync(0xffffffffu, m, 16));
            float s = 0.f;
#pragma unroll
            for (int mi = 0; mi < 4; mi++) {
                s += __expf(acc[mi][ni][par] - m);
                s += __expf(acc[mi][ni][2 + par] - m);
            }
            s += __shfl_xor_sync(0xffffffffu, s, 4);
            s += __shfl_xor_sync(0xffffffffu, s, 8);
            s += __shfl_xor_sync(0xffffffffu, s, 16);
            mcol[ni][par] = m;
            scol[ni][par] = s;
        }
    }
    if (l4 == 0) {
#pragma unroll
        for (int ni = 0; ni < 4; ni++)
#pragma unroll
            for (int par = 0; par < 2; par++) {
                int col = wc + ni * 8 + l2 + par;
                msm[(wid & 1) * 128 + col] = mcol[ni][par];
                ssm[(wid & 1) * 128 + col] = scol[ni][par];
            }
    }
    __syncthreads();
    if (tid < 128) {
        float m0 = msm[tid], m1 = msm[128 + tid];
        float s0 = ssm[tid], s1 = ssm[128 + tid];
        float m = fmaxf(m0, m1);
        float s = s0 * __expf(m0 - m) + s1 * __expf(m1 - m);
        size_t off = (((size_t)bh * 8 + qt) << 10) + k0 + tid;
        pm[off] = m;
        ps[off] = s;
    }
}

// ================= merge per-qtile partials into cm / ics =======================
__global__ void merge_stats(const float* __restrict__ pm, const float* __restrict__ ps,
                            float* __restrict__ cm, float* __restrict__ ics)
{
    int idx = blockIdx.x * 256 + threadIdx.x;    // 64*1024
    int bh = idx >> 10, k = idx & 1023;
    const float* pmb = pm + (((size_t)bh * 8) << 10) + k;
    const float* psb = ps + (((size_t)bh * 8) << 10) + k;
    float m = pmb[0], s = psb[0];
#pragma unroll
    for (int qt = 1; qt < 8; qt++) {
        float m2 = pmb[(size_t)qt << 10];
        float s2 = psb[(size_t)qt << 10];
        float mn = fmaxf(m, m2);
        s = s * __expf(m - mn) + s2 * __expf(m2 - mn);
        m = mn;
    }
    cm[idx] = m;
    ics[idx] = 1.0f / s;
}

// ================= fused attnout: exp-normalize + 3-term split MMA ==============
#define AF_CM   0
#define AF_ICS  4096
#define AF_DEG  8192
#define AF_PH   8320
#define AF_PL   24704
#define AF_VH   41088
#define AF_VL   53376
#define AF_SMEM 65664

__global__ __launch_bounds__(256)
void attnout_fused(const float* __restrict__ w, const float* __restrict__ cm,
                   const float* __restrict__ ics, const __nv_bfloat16* __restrict__ vt,
                   float* __restrict__ o)
{
    extern __shared__ char smem[];
    const uint32_t sb = smem_u32(smem);
    float* cmS  = (float*)(smem + AF_CM);
    float* icsS = (float*)(smem + AF_ICS);
    int*   degS = (int*)(smem + AF_DEG);

    const int bh = blockIdx.y, b = bh >> 3, h = bh & 7;
    const int q0 = blockIdx.x << 7;
    const int tid = threadIdx.x, wid = tid >> 5, lid = tid & 31;
    const int wr = (wid & 1) << 6;
    const int wc = (wid >> 1) * 24;
    const int a_row = (lid & 7) + ((lid >> 3) & 1) * 8;
    const int a_kb  = (lid >> 4) * 8;
    const int b_row = (lid & 7);
    const int b_kb  = ((lid >> 3) & 1) * 8;

    for (int i = tid; i < SS; i += 256) {
        cmS[i]  = cm[bh * SS + i];
        icsS[i] = ics[bh * SS + i];
    }
    __syncthreads();
    if (tid < 16) {
        int d = 0;
        for (int j = 0; j < 64; j++)
            if (cmS[tid * 64 + j] == -1e9f) d = 1;
        degS[tid] = d;
    }
    __syncthreads();

    float acc[4][3][4];
#pragma unroll
    for (int mi = 0; mi < 4; mi++)
#pragma unroll
        for (int ni = 0; ni < 3; ni++)
#pragma unroll
            for (int r = 0; r < 4; r++) acc[mi][ni][r] = 0.f;

    const float* wb = w + (size_t)bh * SS * SS;
    const __nv_bfloat16* Vb = vt + (size_t)(b * DD + h * DKK) * 2048;

    const int pr = tid >> 2;            // rows pr and pr+64
    const int pc = (tid & 3) << 2;
    const bool padA = (g_mask[b * SS + q0 + pr] != 0);
    const bool padB = (g_mask[b * SS + q0 + pr + 64] != 0);

    for (int kc = 0; kc < 16; kc++) {
        bool full = (kc << 6) > q0 + 127;
        if (full && !degS[kc]) continue;

        // ---- build ph / pl chunks [128 q][64 k]
#pragma unroll
        for (int rr = 0; rr < 2; rr++) {
            int r = pr + rr * 64;
            bool an = full || (rr ? padB : padA);   // analytic row: no w read
            const float* wp = wb + (size_t)(q0 + r) * SS + (kc << 6);
#pragma unroll
            for (int i = 0; i < 4; i++) {
                int c4 = pc + i;
                float4 v;
                if (!an) v = *(const float4*)(wp + (c4 << 2));
                float p[4];
#pragma unroll
                for (int e = 0; e < 4; e++) {
                    int k = (kc << 6) + (c4 << 2) + e;
                    if (an) p[e] = (cmS[k] == -1e9f) ? icsS[k] : 0.f;
                    else    p[e] = __expf(((const float*)&v)[e] - cmS[k]) * icsS[k];
                }
                __nv_bfloat16 hh[4], ll[4];
#pragma unroll
                for (int e = 0; e < 4; e++) {
                    hh[e] = __float2bfloat16(p[e]);
                    ll[e] = __float2bfloat16(p[e] - __bfloat162float(hh[e]));
                }
                uint32_t off = SWZ128((uint32_t)((r << 7) + (c4 << 3)));
                *(uint2*)(smem + AF_PH + off) = *(uint2*)hh;
                *(uint2*)(smem + AF_PL + off) = *(uint2*)ll;
            }
        }
        // ---- load V chunks [96 n][64 k] hi & lo
#pragma unroll
        for (int t = 0; t < 3; t++) {
            int n = (tid >> 3) + t * 32;
            int c8 = tid & 7;
            uint32_t off = SWZ128((uint32_t)((n << 7) + (c8 << 4)));
            *(uint4*)(smem + AF_VH + off) =
                *(const uint4*)(Vb + (size_t)n * 2048 + (kc << 6) + (c8 << 3));
            *(uint4*)(smem + AF_VL + off) =
                *(const uint4*)(Vb + (size_t)n * 2048 + 1024 + (kc << 6) + (c8 << 3));
        }
        __syncthreads();

        // ---- 3 sub-GEMMs of BK=64
#pragma unroll
        for (int sub = 0; sub < 3; sub++) {
            const uint32_t sA = sb + ((sub < 2) ? AF_PH : AF_PL);
            const uint32_t sB = sb + ((sub == 1) ? AF_VL : AF_VH);
#pragma unroll
            for (int kk = 0; kk < 4; kk++) {
                uint32_t af[4][4], bf[3][2];
#pragma unroll
                for (int mi = 0; mi < 4; mi++) {
                    uint32_t off = (uint32_t)(((wr + mi * 16 + a_row) << 7) +
                                              ((kk * 16 + a_kb) << 1));
                    asm volatile("ldmatrix.sync.aligned.m8n8.x4.shared.b16 {%0,%1,%2,%3}, [%4];"
                                 : "=r"(af[mi][0]), "=r"(af[mi][1]), "=r"(af[mi][2]), "=r"(af[mi][3])
                                 : "r"(sA + SWZ128(off)));
                }
#pragma unroll
                for (int ni = 0; ni < 3; ni++) {
                    uint32_t off = (uint32_t)(((wc + ni * 8 + b_row) << 7) +
                                              ((kk * 16 + b_kb) << 1));
                    asm volatile("ldmatrix.sync.aligned.m8n8.x2.shared.b16 {%0,%1}, [%2];"
                                 : "=r"(bf[ni][0]), "=r"(bf[ni][1])
                                 : "r"(sB + SWZ128(off)));
                }
#pragma unroll
                for (int mi = 0; mi < 4; mi++)
#pragma unroll
                    for (int ni = 0; ni < 3; ni++) {
                        asm volatile(
                            "mma.sync.aligned.m16n8k16.row.col.f32.bf16.bf16.f32 "
                            "{%0,%1,%2,%3}, {%4,%5,%6,%7}, {%8,%9}, {%0,%1,%2,%3};"
                            : "+f"(acc[mi][ni][0]), "+f"(acc[mi][ni][1]),
                              "+f"(acc[mi][ni][2]), "+f"(acc[mi][ni][3])
                            : "r"(af[mi][0]), "r"(af[mi][1]), "r"(af[mi][2]), "r"(af[mi][3]),
                              "r"(bf[ni][0]), "r"(bf[ni][1]));
                    }
            }
        }
        __syncthreads();
    }

    const int l4 = lid >> 2, l2 = (lid & 3) << 1;
#pragma unroll
    for (int mi = 0; mi < 4; mi++) {
#pragma unroll
        for (int ni = 0; ni < 3; ni++) {
            int rg = b * SS + q0 + wr + mi * 16 + l4;
            int cg = h * DKK + wc + ni * 8 + l2;
            *(float2*)(o + (size_t)rg * DD + cg) =
                make_float2(acc[mi][ni][0], acc[mi][ni][1]);
            *(float2*)(o + (size_t)(rg + 8) * DD + cg) =
                make_float2(acc[mi][ni][2], acc[mi][ni][3]);
        }
    }
}

// ================= mask canonicalization ========================================
__global__ void detect_mask_kernel(const unsigned char* __restrict__ m)
{
    __shared__ int s_big, s_mis;
    if (threadIdx.x == 0) { s_big = 0; s_mis = 0; }
    __syncthreads();
    int big = 0, mis = 0;
    for (int i = threadIdx.x; i < NR; i += blockDim.x) {
        unsigned char v = m[i];
        if (v > 1) big = 1;
        if ((i & 3) != 0 && v != 0) mis = 1;
    }
    if (big) atomicOr(&s_big, 1);
    if (mis) atomicOr(&s_mis, 1);
    __syncthreads();
    if (threadIdx.x == 0) { g_flags[0] = s_big; g_flags[1] = s_mis; }
}

__global__ void convert_mask_kernel(const void* __restrict__ m)
{
    int i = blockIdx.x * blockDim.x + threadIdx.x;
    bool word32 = (g_flags[0] != 0) || (g_flags[1] == 0);
    unsigned char out;
    if (word32) out = (((const unsigned int*)m)[i] != 0u) ? 1 : 0;
    else        out = (((const unsigned char*)m)[i] != 0) ? 1 : 0;
    g_mask[i] = out;
}

// ================= residual add + layernorm (optional fused A-split) ============
template <bool SPLIT>
__global__ __launch_bounds__(256)
void addln_kernel(const float* __restrict__ a, const float* __restrict__ r,
                  const float* __restrict__ g, const float* __restrict__ beta,
                  float* __restrict__ out, __nv_bfloat16* __restrict__ sp)
{
    const int row = blockIdx.x;
    const int tid = threadIdx.x;
    const float* ap = a + (size_t)row * DD;
    const float* rp = r + (size_t)row * DD;

    float v[3];
    float sum = 0.f, sq = 0.f;
#pragma unroll
    for (int i = 0; i < 3; i++) {
        int c = tid + (i << 8);
        v[i] = ap[c] + rp[c];
        sum += v[i];
        sq  += v[i] * v[i];
    }
#pragma unroll
    for (int off = 16; off > 0; off >>= 1) {
        sum += __shfl_xor_sync(0xffffffffu, sum, off);
        sq  += __shfl_xor_sync(0xffffffffu, sq,  off);
    }
    __shared__ float s1[8], s2[8];
    int warp = tid >> 5, lane = tid & 31;
    if (lane == 0) { s1[warp] = sum; s2[warp] = sq; }
    __syncthreads();
    if (warp == 0) {
        float aa = (lane < 8) ? s1[lane] : 0.f;
        float bb = (lane < 8) ? s2[lane] : 0.f;
#pragma unroll
        for (int off = 4; off > 0; off >>= 1) {
            aa += __shfl_xor_sync(0xffffffffu, aa, off);
            bb += __shfl_xor_sync(0xffffffffu, bb, off);
        }
        if (lane == 0) { s1[0] = aa; s2[0] = bb; }
    }
    __syncthreads();
    const float invD = 1.0f / 768.0f;
    float mean = s1[0] * invD;
    float var  = s2[0] * invD - mean * mean;
    float inv  = rsqrtf(var + 1e-5f);
#pragma unroll
    for (int i = 0; i < 3; i++) {
        int c = tid + (i << 8);
        float y = (v[i] - mean) * inv * g[c] + beta[c];
        out[(size_t)row * DD + c] = y;
        if (SPLIT) {
            __nv_bfloat16 h = __float2bfloat16(y);
            __nv_bfloat16 l = __float2bfloat16(y - __bfloat162float(h));
            __nv_bfloat16* op = sp + (size_t)row * 2304;
            op[c] = h; op[768 + c] = h; op[1536 + c] = l;
        }
    }
}

// ================= host side ====================================================
static void run_mha(const float* Wq, const float* bq,
                    const float* Wv, const float* bv,
                    const float* g, const float* beta,
                    const float* xin, float* xout,
                    __nv_bfloat16* a2, __nv_bfloat16* a2next, __nv_bfloat16* b2t,
                    __nv_bfloat16* qs, __nv_bfloat16* ks, __nv_bfloat16* vt,
                    float* kv, float* w,
                    float* cm, float* ics, float* pmb, float* psb,
                    float* o)
{
    split_wt_kernel<<<dim3(DD / 32, DD / 32), dim3(32, 8)>>>(Wq, b2t, DD, DD);
    mma_gemm<2><<<dim3(DD / 128, NR / 128), 256, GEMM_SMEM_BYTES>>>(a2, b2t, bq, nullptr, qs, DD, 2304);
    split_wt_kernel<<<dim3(DD / 32, DD / 32), dim3(32, 8)>>>(Wv, b2t, DD, DD);
    mma_gemm<3><<<dim3(DD / 128, NR / 128), 256, GEMM_SMEM_BYTES>>>(a2, b2t, bv, kv, ks, DD, 2304);
    split_vt_kernel<<<dim3(DD / 32, SS / 32, BB), dim3(32, 8)>>>(kv, vt);
    scores_mma<<<dim3(SS / 128, SS / 128, NBH), 256, GEMM_SMEM_BYTES>>>(qs, ks, w, pmb, psb);
    merge_stats<<<NBH * SS / 256, 256>>>(pmb, psb, cm, ics);
    attnout_fused<<<dim3(SS / 128, NBH), 256, AF_SMEM>>>(w, cm, ics, vt, o);
    addln_kernel<true><<<NR, 256>>>(o, xin, g, beta, xout, a2next);
}

extern "C" void kernel_launch(void* const* d_in, const int* in_sizes, int n_in,
                              void* d_out, int out_size)
{
    (void)in_sizes; (void)n_in; (void)out_size;

    const float* x     = (const float*)d_in[0];
    const void*  amraw = d_in[1];
    const float* a1_Wq = (const float*)d_in[2];
    const float* a1_bq = (const float*)d_in[3];
    const float* a1_Wv = (const float*)d_in[4];
    const float* a1_bv = (const float*)d_in[5];
    const float* a1_g  = (const float*)d_in[6];
    const float* a1_b  = (const float*)d_in[7];
    const float* a2_Wq = (const float*)d_in[8];
    const float* a2_bq = (const float*)d_in[9];
    const float* a2_Wv = (const float*)d_in[10];
    const float* a2_bv = (const float*)d_in[11];
    const float* a2_g  = (const float*)d_in[12];
    const float* a2_b  = (const float*)d_in[13];
    const float* f_W1  = (const float*)d_in[14];
    const float* f_b1  = (const float*)d_in[15];
    const float* f_W2  = (const float*)d_in[16];
    const float* f_b2  = (const float*)d_in[17];
    const float* f_g   = (const float*)d_in[18];
    const float* f_b   = (const float*)d_in[19];
    float* out = (float*)d_out;

    float *kv, *w, *cm, *ics, *pmb, *psb, *o, *x1, *x2;
    __nv_bfloat16 *a2buf, *a2h, *b2t, *qs, *ks, *vt;
    cudaGetSymbolAddress((void**)&kv,    g_kv);
    cudaGetSymbolAddress((void**)&w,     g_w);
    cudaGetSymbolAddress((void**)&cm,    g_cm);
    cudaGetSymbolAddress((void**)&ics,   g_ics);
    cudaGetSymbolAddress((void**)&pmb,   g_pm);
    cudaGetSymbolAddress((void**)&psb,   g_ps);
    cudaGetSymbolAddress((void**)&o,     g_o);
    cudaGetSymbolAddress((void**)&x1,    g_x1);
    cudaGetSymbolAddress((void**)&x2,    g_x2);
    cudaGetSymbolAddress((void**)&a2buf, g_a2);
    cudaGetSymbolAddress((void**)&a2h,   g_a2h);
    cudaGetSymbolAddress((void**)&b2t,   g_b2t);
    cudaGetSymbolAddress((void**)&qs,    g_qs);
    cudaGetSymbolAddress((void**)&ks,    g_ks);
    cudaGetSymbolAddress((void**)&vt,    g_vt);

    cudaFuncSetAttribute(mma_gemm<0>,  cudaFuncAttributeMaxDynamicSharedMemorySize, GEMM_SMEM_BYTES);
    cudaFuncSetAttribute(mma_gemm<2>,  cudaFuncAttributeMaxDynamicSharedMemorySize, GEMM_SMEM_BYTES);
    cudaFuncSetAttribute(mma_gemm<3>,  cudaFuncAttributeMaxDynamicSharedMemorySize, GEMM_SMEM_BYTES);
    cudaFuncSetAttribute(mma_gemm<4>,  cudaFuncAttributeMaxDynamicSharedMemorySize, GEMM_SMEM_BYTES);
    cudaFuncSetAttribute(scores_mma,   cudaFuncAttributeMaxDynamicSharedMemorySize, GEMM_SMEM_BYTES);
    cudaFuncSetAttribute(attnout_fused,cudaFuncAttributeMaxDynamicSharedMemorySize, AF_SMEM);

    detect_mask_kernel<<<1, 256>>>((const unsigned char*)amraw);
    convert_mask_kernel<<<NR / 256, 256>>>(amraw);

    // initial A split for layer-1 (subsequent splits produced by fused epilogues)
    split_a_kernel<<<NR * DD / 256, 256>>>(x, a2buf, DD);

    run_mha(a1_Wq, a1_bq, a1_Wv, a1_bv, a1_g, a1_b, x,  x1,
            a2buf, a2buf, b2t, qs, ks, vt, kv, w, cm, ics, pmb, psb, o);
    run_mha(a2_Wq, a2_bq, a2_Wv, a2_bv, a2_g, a2_b, x1, x2,
            a2buf, a2buf, b2t, qs, ks, vt, kv, w, cm, ics, pmb, psb, o);

    // FFN
    split_wt_kernel<<<dim3(FFD / 32, DD / 32), dim3(32, 8)>>>(f_W1, b2t, DD, FFD);
    mma_gemm<4><<<dim3(FFD / 128, NR / 128), 256, GEMM_SMEM_BYTES>>>(a2buf, b2t, f_b1, nullptr, a2h, FFD, 2304);
    split_wt_kernel<<<dim3(DD / 32, FFD / 32), dim3(32, 8)>>>(f_W2, b2t, FFD, DD);
    mma_gemm<0><<<dim3(DD / 128, NR / 128), 256, GEMM_SMEM_BYTES>>>(a2h, b2t, f_b2, o, nullptr, DD, 3072);
    addln_kernel<false><<<NR, 256>>>(o, x2, f_g, f_b, out, nullptr);
}